// round 13
// baseline (speedup 1.0000x reference)
#include <cuda_runtime.h>
#include <cstdint>

#define BB_ 8
#define CC_ 256
#define HH_ 128
#define WW_ 128
#define NPIX (BB_*HH_*WW_)   // 131072
#define HW_ (HH_*WW_)        // 16384

// Bit-packed scratch. Per pixel: 8 uint32 words (= 2 uint4); bit i of word wd
// = channel wd*32+i, 1 <=> value >= 0.
__device__ uint4 g_xbits[NPIX*2];       // 4 MB  binarized input
__device__ uint4 g_mbits[NPIX*2];       // 4 MB  binarized mid
__device__ uint4 g_wb  [4*5*64*2];      // branch weights: [br][k][o][2]
__device__ uint4 g_wcb [9*256*2];       // main weights:   [t][o][2]
__device__ int   g_one = 1;             // opaque 1: forces mad.lo to stay IMAD (fma pipe)

__device__ __forceinline__ unsigned x3(unsigned a, unsigned b, unsigned c) {
    unsigned r; asm("lop3.b32 %0, %1, %2, %3, 0x96;" : "=r"(r) : "r"(a), "r"(b), "r"(c)); return r;
}
__device__ __forceinline__ unsigned mj(unsigned a, unsigned b, unsigned c) {
    unsigned r; asm("lop3.b32 %0, %1, %2, %3, 0xE8;" : "=r"(r) : "r"(a), "r"(b), "r"(c)); return r;
}

// CSA-compressed 8-word xor-popcount accumulate: acc += sum_i popc(x_i ^ w_i).
// alu pipe: 8 XOR + 8 LOP3 (nothing else); popc pipe: 4 POPC;
// fma pipe: 4 IMAD (weighted combine chained into acc; 'one' keeps them IMAD).
__device__ __forceinline__ void cdot8_acc(int& acc, int one, uint4 xa, uint4 xb, uint4 wa, uint4 wb) {
    unsigned v0 = xa.x^wa.x, v1 = xa.y^wa.y, v2 = xa.z^wa.z, v3 = xa.w^wa.w;
    unsigned v4 = xb.x^wb.x, v5 = xb.y^wb.y, v6 = xb.z^wb.z, v7 = xb.w^wb.w;
    unsigned s0 = x3(v0, v1, v2), c0 = mj(v0, v1, v2);
    unsigned s1 = x3(v3, v4, v5), c1 = mj(v3, v4, v5);
    unsigned s2 = x3(s0, s1, v6), c2 = mj(s0, s1, v6);
    unsigned s3 = x3(c0, c1, c2), c3 = mj(c0, c1, c2);
    asm("mad.lo.s32 %0, %1, %2, %0;" : "+r"(acc) : "r"(__popc(s2)), "r"(one));
    asm("mad.lo.s32 %0, %1, %2, %0;" : "+r"(acc) : "r"(__popc(v7)), "r"(one));
    asm("mad.lo.s32 %0, %1, 2, %0;"  : "+r"(acc) : "r"(__popc(s3)));
    asm("mad.lo.s32 %0, %1, 4, %0;"  : "+r"(acc) : "r"(__popc(c3)));
}
__device__ __forceinline__ int popc8w(uint4 a, uint4 b) {
    return __popc(a.x) + __popc(a.y) + __popc(a.z) + __popc(a.w)
         + __popc(b.x) + __popc(b.y) + __popc(b.z) + __popc(b.w);
}

// ---------------------------------------------------------------------------
__global__ __launch_bounds__(256) void pack_x(const float* __restrict__ x) {
    int tid = blockIdx.x*256 + threadIdx.x;
    int wd  = tid >> 17;
    int pix = tid & (NPIX-1);
    int b   = pix >> 14;
    int hw  = pix & (HW_-1);
    const float* p = x + ((size_t)(b*CC_ + wd*32))*HW_ + hw;
    unsigned bits = 0;
    #pragma unroll
    for (int i = 0; i < 32; i++)
        if (p[(size_t)i*HW_] >= 0.f) bits |= (1u << i);
    ((unsigned*)g_xbits)[pix*8 + wd] = bits;
}

// ---------------------------------------------------------------------------
__global__ __launch_bounds__(256) void pack_w(
    const float* __restrict__ w1, const float* __restrict__ w2,
    const float* __restrict__ w3, const float* __restrict__ w4,
    const float* __restrict__ wc)
{
    int tid = blockIdx.x*256 + threadIdx.x;
    if (tid < 4*5*64*8) {
        int wd = tid & 7;
        int o  = (tid >> 3) & 63;
        int kk = tid >> 9;          // br*5 + k
        int k  = kk % 5, br = kk / 5;
        const float* src = (br==0) ? w1 : (br==1) ? w2 : (br==2) ? w3 : w4;
        unsigned bits = 0;
        #pragma unroll
        for (int i = 0; i < 32; i++) {
            int c = wd*32 + i;
            float v = src[(o*CC_ + c)*5 + k];
            if (v >= 0.f) bits |= (1u << i);
        }
        ((unsigned*)g_wb)[tid] = bits;
    } else {
        int j = tid - 4*5*64*8;
        if (j < 9*256*8) {
            int wd = j & 7;
            int o  = (j >> 3) & 255;
            int t  = j >> 11;
            unsigned bits = 0;
            #pragma unroll
            for (int i = 0; i < 32; i++) {
                int c = wd*32 + i;
                float v = wc[(o*CC_ + c)*9 + t];
                if (v >= 0.f) bits |= (1u << i);
            }
            ((unsigned*)g_wcb)[j] = bits;
        }
    }
}

// ---------------------------------------------------------------------------
// Branch convs. Block = 32-px row strip, 512 thr.
// warpid: br = warpid & 3, q = warpid >> 2 (8-px quarter).
// Each lane computes oc = lane and oc+32 of its branch.
__global__ __launch_bounds__(512, 2) void branch_conv(
    const float* __restrict__ b1, const float* __restrict__ b2,
    const float* __restrict__ b3, const float* __restrict__ b4,
    const float* __restrict__ a1p)
{
    __shared__ uint4 xt[9*40*2];    // rows h-4..h+4, cols w0-4..w0+35
    const int bx = blockIdx.x, h = blockIdx.y, bb = blockIdx.z;
    const int w0 = bx*32;
    const int tid = threadIdx.x, lane = tid & 31;
    const int br = (tid >> 5) & 3, q = tid >> 7, px0 = q*8;
    const int one = g_one;

    for (int i = tid; i < 9*40; i += 512) {
        int r = i / 40, c = i % 40;
        int hh = h - 4 + r, ww = w0 - 4 + c;
        uint4 v0 = make_uint4(0,0,0,0), v1 = v0;
        if ((unsigned)hh < HH_ && (unsigned)ww < WW_) {
            const uint4* s = g_xbits + ((bb*HH_ + hh)*WW_ + ww)*2;
            v0 = s[0]; v1 = s[1];
        }
        xt[i*2] = v0; xt[i*2+1] = v1;
    }
    __syncthreads();

    const int sh = (br >= 2) ? ((br == 2) ? 1 : 2) : 0;
    const int sw = (br <  2) ? ((br == 0) ? 1 : 2) : 0;
    const bool edge = (br < 2) ? (bx == 0 || bx == 3) : (h < 4 || h > 123);

    int acc[16];                    // [0..7] oc=lane, [8..15] oc=lane+32
    #pragma unroll
    for (int p = 0; p < 16; p++) acc[p] = 0;

    #pragma unroll 1
    for (int k = 0; k < 5; k++) {
        const uint4* wpA = g_wb + ((br*5 + k)*64 + lane)*2;
        const uint4* wpB = wpA + 64;               // oc+32
        uint4 wA0 = wpA[0], wA1 = wpA[1];
        uint4 wB0 = wpB[0], wB1 = wpB[1];
        int d = k - 2;
        const uint4* s = xt + ((4 + d*sh)*40 + 4 + d*sw + px0)*2;
        #pragma unroll
        for (int p = 0; p < 8; p++) {
            uint4 x0 = s[2*p], x1 = s[2*p+1];
            cdot8_acc(acc[p],   one, x0, x1, wA0, wA1);
            cdot8_acc(acc[8+p], one, x0, x1, wB0, wB1);
        }
    }
    if (edge) {
        #pragma unroll 1
        for (int k = 0; k < 5; k++) {
            const uint4* wpA = g_wb + ((br*5 + k)*64 + lane)*2;
            const uint4* wpB = wpA + 64;
            int pwA = popc8w(wpA[0], wpA[1]);
            int pwB = popc8w(wpB[0], wpB[1]);
            int d = k - 2;
            bool hInv = ((unsigned)(h + d*sh) >= HH_);
            #pragma unroll
            for (int p = 0; p < 8; p++) {
                int ww = w0 + px0 + p + d*sw;
                if (hInv || (unsigned)ww >= WW_) {
                    acc[p]   += 128 - pwA;
                    acc[8+p] += 128 - pwB;
                }
            }
        }
    }

    const float* bp = (br==0) ? b1 : (br==1) ? b2 : (br==2) ? b3 : b4;
    const float biasA = bp[lane], biasB = bp[lane + 32];
    const float a1 = a1p[0];
    unsigned* mout = (unsigned*)g_mbits + ((bb*HH_ + h)*WW_ + w0 + px0)*8 + br*2;
    #pragma unroll
    for (int p = 0; p < 8; p++) {
        float vA = (float)(1280 - 2*acc[p])   + biasA;
        float vB = (float)(1280 - 2*acc[8+p]) + biasB;
        float pA = (vA >= 0.f) ? vA : a1*vA;
        float pB = (vB >= 0.f) ? vB : a1*vB;
        unsigned mA = __ballot_sync(0xffffffffu, pA >= 0.f);
        unsigned mB = __ballot_sync(0xffffffffu, pB >= 0.f);
        if (lane == 0) { mout[p*8] = mA; mout[p*8 + 1] = mB; }
    }
}

// ---------------------------------------------------------------------------
// Main 3x3 conv + bias + prelu + residual. Block = 32-px row strip, 512 thr.
// tid = half*256 + oc; thread owns 16 px of one oc. Rolling-column sweep:
// row-outer (3 taps' weights live), 18-column inner; each loaded column
// immediately feeds up to 3 pixel accumulators.
__global__ __launch_bounds__(512, 2) void main_conv(
    const float* __restrict__ x, const float* __restrict__ bc,
    const float* __restrict__ a2p, float* __restrict__ out)
{
    __shared__ uint4 xt[3*34*2];    // rows h-1..h+1, cols w0-1..w0+32
    const int bx = blockIdx.x, h = blockIdx.y, bb = blockIdx.z;
    const int w0 = bx*32;
    const int tid = threadIdx.x;
    const int oc = tid & 255, half = tid >> 8, px0 = half*16;
    const int one = g_one;

    for (int i = tid; i < 3*34; i += 512) {
        int r = i / 34, c = i % 34;
        int hh = h - 1 + r, ww = w0 - 1 + c;
        uint4 v0 = make_uint4(0,0,0,0), v1 = v0;
        if ((unsigned)hh < HH_ && (unsigned)ww < WW_) {
            const uint4* s = g_mbits + ((bb*HH_ + hh)*WW_ + ww)*2;
            v0 = s[0]; v1 = s[1];
        }
        xt[i*2] = v0; xt[i*2+1] = v1;
    }
    __syncthreads();

    int acc[16];
    #pragma unroll
    for (int p = 0; p < 16; p++) acc[p] = 0;

    #pragma unroll 1
    for (int r = 0; r < 3; r++) {
        const uint4* wp0 = g_wcb + ((r*3 + 0)*256 + oc)*2;
        const uint4* wp1 = g_wcb + ((r*3 + 1)*256 + oc)*2;
        const uint4* wp2 = g_wcb + ((r*3 + 2)*256 + oc)*2;
        uint4 w00 = wp0[0], w01 = wp0[1];
        uint4 w10 = wp1[0], w11 = wp1[1];
        uint4 w20 = wp2[0], w21 = wp2[1];
        const uint4* srow = xt + (r*34 + px0)*2;
        #pragma unroll
        for (int jj = 0; jj < 18; jj++) {
            uint4 x0 = srow[2*jj], x1 = srow[2*jj+1];
            if (jj >= 2)             cdot8_acc(acc[jj-2], one, x0, x1, w20, w21);
            if (jj >= 1 && jj <= 16) cdot8_acc(acc[jj-1], one, x0, x1, w10, w11);
            if (jj <= 15)            cdot8_acc(acc[jj],   one, x0, x1, w00, w01);
        }
    }
    const bool edge = (h == 0) | (h == 127) | (bx == 0) | (bx == 3);
    if (edge) {
        #pragma unroll 1
        for (int t = 0; t < 9; t++) {
            const uint4* wp = g_wcb + (t*256 + oc)*2;
            int pw = popc8w(wp[0], wp[1]);
            bool hInv = ((unsigned)(h + t/3 - 1) >= HH_);
            int dw = t%3 - 1;
            #pragma unroll
            for (int p = 0; p < 16; p++) {
                int ww = w0 + px0 + p + dw;
                if (hInv || (unsigned)ww >= WW_) acc[p] += 128 - pw;
            }
        }
    }

    const float a2 = a2p[0];
    const float bias = bc[oc];
    const size_t gbase = (((size_t)bb*CC_ + oc)*HH_ + h)*WW_ + w0 + px0;
    #pragma unroll
    for (int q = 0; q < 4; q++) {
        float4 xr = *(const float4*)(x + gbase + q*4);
        float4 o4;
        float v0 = (float)(2304 - 2*acc[q*4+0]) + bias; v0 = (v0 >= 0.f) ? v0 : a2*v0;
        float v1 = (float)(2304 - 2*acc[q*4+1]) + bias; v1 = (v1 >= 0.f) ? v1 : a2*v1;
        float v2 = (float)(2304 - 2*acc[q*4+2]) + bias; v2 = (v2 >= 0.f) ? v2 : a2*v2;
        float v3 = (float)(2304 - 2*acc[q*4+3]) + bias; v3 = (v3 >= 0.f) ? v3 : a2*v3;
        o4.x = v0 + xr.x; o4.y = v1 + xr.y; o4.z = v2 + xr.z; o4.w = v3 + xr.w;
        *(float4*)(out + gbase + q*4) = o4;
    }
}

// ---------------------------------------------------------------------------
extern "C" void kernel_launch(void* const* d_in, const int* in_sizes, int n_in,
                              void* d_out, int out_size) {
    const float* x  = (const float*)d_in[0];
    const float* w1 = (const float*)d_in[1];
    const float* b1 = (const float*)d_in[2];
    const float* w2 = (const float*)d_in[3];
    const float* b2 = (const float*)d_in[4];
    const float* w3 = (const float*)d_in[5];
    const float* b3 = (const float*)d_in[6];
    const float* w4 = (const float*)d_in[7];
    const float* b4 = (const float*)d_in[8];
    const float* a1 = (const float*)d_in[9];
    const float* wc = (const float*)d_in[10];
    const float* bc = (const float*)d_in[11];
    const float* a2 = (const float*)d_in[12];
    float* out = (float*)d_out;

    pack_x<<<4096, 256>>>(x);
    pack_w<<<112, 256>>>(w1, w2, w3, w4, wc);
    branch_conv<<<dim3(4,128,8), 512>>>(b1, b2, b3, b4, a1);
    main_conv<<<dim3(4,128,8), 512>>>(x, bc, a2, out);
}

// round 14
// speedup vs baseline: 1.0413x; 1.0413x over previous
#include <cuda_runtime.h>
#include <cstdint>

#define BB_ 8
#define CC_ 256
#define HH_ 128
#define WW_ 128
#define NPIX (BB_*HH_*WW_)   // 131072
#define HW_ (16384)

// Bit-packed scratch. Per pixel: 8 uint32 words (= 2 uint4); bit i of word wd
// = channel wd*32+i, 1 <=> value >= 0.
__device__ uint4 g_xbits[NPIX*2];       // 4 MB  binarized input
__device__ uint4 g_mbits[NPIX*2];       // 4 MB  binarized mid
__device__ uint4 g_wb  [4*5*64*2];      // branch weights: [br][k][o][2]
__device__ uint4 g_wcb [9*256*2];       // main weights:   [t][o][2]
__device__ int   g_pwb [4*5*64];        // branch weight popcounts [br*5+k][o]
__device__ int   g_pwc [9*256];         // main weight popcounts   [t][o]

__device__ __forceinline__ unsigned x3(unsigned a, unsigned b, unsigned c) {
    unsigned r; asm("lop3.b32 %0, %1, %2, %3, 0x96;" : "=r"(r) : "r"(a), "r"(b), "r"(c)); return r;
}
__device__ __forceinline__ unsigned mj(unsigned a, unsigned b, unsigned c) {
    unsigned r; asm("lop3.b32 %0, %1, %2, %3, 0xE8;" : "=r"(r) : "r"(a), "r"(b), "r"(c)); return r;
}

// CSA-compressed 8-word xor-popcount accumulate (R12 combine shape):
// alu: 8 XOR + 8 LOP3 + 1 IADD3; popc: 4 POPC; fma: 2 IMAD (independent).
__device__ __forceinline__ void cdot8_acc(int& acc, uint4 xa, uint4 xb, uint4 wa, uint4 wb) {
    unsigned v0 = xa.x^wa.x, v1 = xa.y^wa.y, v2 = xa.z^wa.z, v3 = xa.w^wa.w;
    unsigned v4 = xb.x^wb.x, v5 = xb.y^wb.y, v6 = xb.z^wb.z, v7 = xb.w^wb.w;
    unsigned s0 = x3(v0, v1, v2), c0 = mj(v0, v1, v2);
    unsigned s1 = x3(v3, v4, v5), c1 = mj(v3, v4, v5);
    unsigned s2 = x3(s0, s1, v6), c2 = mj(s0, s1, v6);
    unsigned s3 = x3(c0, c1, c2), c3 = mj(c0, c1, c2);
    int t1, t2;
    asm("mad.lo.s32 %0, %1, 2, %2;" : "=r"(t1) : "r"(__popc(s3)), "r"(__popc(s2)));
    asm("mad.lo.s32 %0, %1, 4, %2;" : "=r"(t2) : "r"(__popc(c3)), "r"(__popc(v7)));
    acc = acc + t1 + t2;
}

// ---------------------------------------------------------------------------
__global__ __launch_bounds__(256) void pack_x(const float* __restrict__ x) {
    int tid = blockIdx.x*256 + threadIdx.x;
    int wd  = tid >> 17;
    int pix = tid & (NPIX-1);
    int b   = pix >> 14;
    int hw  = pix & (HW_-1);
    const float* p = x + ((size_t)(b*CC_ + wd*32))*HW_ + hw;
    unsigned bits = 0;
    #pragma unroll
    for (int i = 0; i < 32; i++)
        if (p[(size_t)i*HW_] >= 0.f) bits |= (1u << i);
    ((unsigned*)g_xbits)[pix*8 + wd] = bits;
}

// ---------------------------------------------------------------------------
// Pack weights + per-(tap,oc) popcount tables (in-warp 8-lane reduction;
// groups of 8 lanes are warp-aligned in both sections).
__global__ __launch_bounds__(256) void pack_w(
    const float* __restrict__ w1, const float* __restrict__ w2,
    const float* __restrict__ w3, const float* __restrict__ w4,
    const float* __restrict__ wc)
{
    int tid = blockIdx.x*256 + threadIdx.x;
    if (tid < 4*5*64*8) {
        int wd = tid & 7;
        int o  = (tid >> 3) & 63;
        int kk = tid >> 9;          // br*5 + k
        int k  = kk % 5, br = kk / 5;
        const float* src = (br==0) ? w1 : (br==1) ? w2 : (br==2) ? w3 : w4;
        unsigned bits = 0;
        #pragma unroll
        for (int i = 0; i < 32; i++) {
            int c = wd*32 + i;
            float v = src[(o*CC_ + c)*5 + k];
            if (v >= 0.f) bits |= (1u << i);
        }
        ((unsigned*)g_wb)[tid] = bits;
        int pc = __popc(bits);
        pc += __shfl_xor_sync(0xffffffffu, pc, 1);
        pc += __shfl_xor_sync(0xffffffffu, pc, 2);
        pc += __shfl_xor_sync(0xffffffffu, pc, 4);
        if (wd == 0) g_pwb[kk*64 + o] = pc;
    } else {
        int j = tid - 4*5*64*8;
        if (j < 9*256*8) {
            int wd = j & 7;
            int o  = (j >> 3) & 255;
            int t  = j >> 11;
            unsigned bits = 0;
            #pragma unroll
            for (int i = 0; i < 32; i++) {
                int c = wd*32 + i;
                float v = wc[(o*CC_ + c)*9 + t];
                if (v >= 0.f) bits |= (1u << i);
            }
            ((unsigned*)g_wcb)[j] = bits;
            int pc = __popc(bits);
            pc += __shfl_xor_sync(0xffffffffu, pc, 1);
            pc += __shfl_xor_sync(0xffffffffu, pc, 2);
            pc += __shfl_xor_sync(0xffffffffu, pc, 4);
            if (wd == 0) g_pwc[t*256 + o] = pc;
        }
    }
}

// ---------------------------------------------------------------------------
// Branch convs. Block = 32-px row strip, 512 thr.
// warpid: br = warpid & 3, q = warpid >> 2 (8-px quarter).
// Each lane computes oc = lane and oc+32 of its branch.
__global__ __launch_bounds__(512, 2) void branch_conv(
    const float* __restrict__ b1, const float* __restrict__ b2,
    const float* __restrict__ b3, const float* __restrict__ b4,
    const float* __restrict__ a1p)
{
    __shared__ uint4 xt[9*40*2];    // rows h-4..h+4, cols w0-4..w0+35
    const int bx = blockIdx.x, h = blockIdx.y, bb = blockIdx.z;
    const int w0 = bx*32;
    const int tid = threadIdx.x, lane = tid & 31;
    const int br = (tid >> 5) & 3, q = tid >> 7, px0 = q*8;

    for (int i = tid; i < 9*40; i += 512) {
        int r = i / 40, c = i % 40;
        int hh = h - 4 + r, ww = w0 - 4 + c;
        uint4 v0 = make_uint4(0,0,0,0), v1 = v0;
        if ((unsigned)hh < HH_ && (unsigned)ww < WW_) {
            const uint4* s = g_xbits + ((bb*HH_ + hh)*WW_ + ww)*2;
            v0 = s[0]; v1 = s[1];
        }
        xt[i*2] = v0; xt[i*2+1] = v1;
    }
    __syncthreads();

    const int sh = (br >= 2) ? ((br == 2) ? 1 : 2) : 0;
    const int sw = (br <  2) ? ((br == 0) ? 1 : 2) : 0;
    const bool edge = (br < 2) ? (bx == 0 || bx == 3) : (h < 4 || h > 123);

    int acc[16];                    // [0..7] oc=lane, [8..15] oc=lane+32
    #pragma unroll
    for (int p = 0; p < 16; p++) acc[p] = 0;

    #pragma unroll 1
    for (int k = 0; k < 5; k++) {
        const uint4* wpA = g_wb + ((br*5 + k)*64 + lane)*2;
        const uint4* wpB = wpA + 64;               // oc+32
        uint4 wA0 = wpA[0], wA1 = wpA[1];
        uint4 wB0 = wpB[0], wB1 = wpB[1];
        int d = k - 2;
        const uint4* s = xt + ((4 + d*sh)*40 + 4 + d*sw + px0)*2;
        #pragma unroll
        for (int p = 0; p < 8; p++) {
            uint4 x0 = s[2*p], x1 = s[2*p+1];
            cdot8_acc(acc[p],   x0, x1, wA0, wA1);
            cdot8_acc(acc[8+p], x0, x1, wB0, wB1);
        }
    }
    if (edge) {
        #pragma unroll 1
        for (int k = 0; k < 5; k++) {
            int pwA = 128 - g_pwb[(br*5 + k)*64 + lane];
            int pwB = 128 - g_pwb[(br*5 + k)*64 + lane + 32];
            int d = k - 2;
            bool hInv = ((unsigned)(h + d*sh) >= HH_);
            #pragma unroll
            for (int p = 0; p < 8; p++) {
                int ww = w0 + px0 + p + d*sw;
                if (hInv || (unsigned)ww >= WW_) {
                    acc[p]   += pwA;
                    acc[8+p] += pwB;
                }
            }
        }
    }

    const float* bp = (br==0) ? b1 : (br==1) ? b2 : (br==2) ? b3 : b4;
    const float biasA = bp[lane], biasB = bp[lane + 32];
    const float a1 = a1p[0];
    unsigned* mout = (unsigned*)g_mbits + ((bb*HH_ + h)*WW_ + w0 + px0)*8 + br*2;
    #pragma unroll
    for (int p = 0; p < 8; p++) {
        float vA = (float)(1280 - 2*acc[p])   + biasA;
        float vB = (float)(1280 - 2*acc[8+p]) + biasB;
        float pA = (vA >= 0.f) ? vA : a1*vA;
        float pB = (vB >= 0.f) ? vB : a1*vB;
        unsigned mA = __ballot_sync(0xffffffffu, pA >= 0.f);
        unsigned mB = __ballot_sync(0xffffffffu, pB >= 0.f);
        if (lane == 0) { mout[p*8] = mA; mout[p*8 + 1] = mB; }
    }
}

// ---------------------------------------------------------------------------
// Main 3x3 conv + bias + prelu + residual. Block = 32-px row strip, 512 thr.
// tid = half*256 + oc; thread owns 16 px of one oc. Rolling-column sweep:
// row-outer (3 taps' weights live), 18-column inner; each loaded column
// immediately feeds up to 3 pixel accumulators.
__global__ __launch_bounds__(512, 2) void main_conv(
    const float* __restrict__ x, const float* __restrict__ bc,
    const float* __restrict__ a2p, float* __restrict__ out)
{
    __shared__ uint4 xt[3*34*2];    // rows h-1..h+1, cols w0-1..w0+32
    const int bx = blockIdx.x, h = blockIdx.y, bb = blockIdx.z;
    const int w0 = bx*32;
    const int tid = threadIdx.x;
    const int oc = tid & 255, half = tid >> 8, px0 = half*16;

    for (int i = tid; i < 3*34; i += 512) {
        int r = i / 34, c = i % 34;
        int hh = h - 1 + r, ww = w0 - 1 + c;
        uint4 v0 = make_uint4(0,0,0,0), v1 = v0;
        if ((unsigned)hh < HH_ && (unsigned)ww < WW_) {
            const uint4* s = g_mbits + ((bb*HH_ + hh)*WW_ + ww)*2;
            v0 = s[0]; v1 = s[1];
        }
        xt[i*2] = v0; xt[i*2+1] = v1;
    }
    __syncthreads();

    int acc[16];
    #pragma unroll
    for (int p = 0; p < 16; p++) acc[p] = 0;

    #pragma unroll 1
    for (int r = 0; r < 3; r++) {
        const uint4* wp0 = g_wcb + ((r*3 + 0)*256 + oc)*2;
        const uint4* wp1 = g_wcb + ((r*3 + 1)*256 + oc)*2;
        const uint4* wp2 = g_wcb + ((r*3 + 2)*256 + oc)*2;
        uint4 w00 = wp0[0], w01 = wp0[1];
        uint4 w10 = wp1[0], w11 = wp1[1];
        uint4 w20 = wp2[0], w21 = wp2[1];
        const uint4* srow = xt + (r*34 + px0)*2;
        #pragma unroll
        for (int jj = 0; jj < 18; jj++) {
            uint4 x0 = srow[2*jj], x1 = srow[2*jj+1];
            if (jj >= 2)             cdot8_acc(acc[jj-2], x0, x1, w20, w21);
            if (jj >= 1 && jj <= 16) cdot8_acc(acc[jj-1], x0, x1, w10, w11);
            if (jj <= 15)            cdot8_acc(acc[jj],   x0, x1, w00, w01);
        }
    }
    const bool edge = (h == 0) | (h == 127) | (bx == 0) | (bx == 3);
    if (edge) {
        #pragma unroll 1
        for (int t = 0; t < 9; t++) {
            int pw = 128 - g_pwc[t*256 + oc];
            bool hInv = ((unsigned)(h + t/3 - 1) >= HH_);
            int dw = t%3 - 1;
            #pragma unroll
            for (int p = 0; p < 16; p++) {
                int ww = w0 + px0 + p + dw;
                if (hInv || (unsigned)ww >= WW_) acc[p] += pw;
            }
        }
    }

    const float a2 = a2p[0];
    const float bias = bc[oc];
    const size_t gbase = (((size_t)bb*CC_ + oc)*HH_ + h)*WW_ + w0 + px0;
    #pragma unroll
    for (int q = 0; q < 4; q++) {
        float4 xr = *(const float4*)(x + gbase + q*4);
        float4 o4;
        float v0 = (float)(2304 - 2*acc[q*4+0]) + bias; v0 = (v0 >= 0.f) ? v0 : a2*v0;
        float v1 = (float)(2304 - 2*acc[q*4+1]) + bias; v1 = (v1 >= 0.f) ? v1 : a2*v1;
        float v2 = (float)(2304 - 2*acc[q*4+2]) + bias; v2 = (v2 >= 0.f) ? v2 : a2*v2;
        float v3 = (float)(2304 - 2*acc[q*4+3]) + bias; v3 = (v3 >= 0.f) ? v3 : a2*v3;
        o4.x = v0 + xr.x; o4.y = v1 + xr.y; o4.z = v2 + xr.z; o4.w = v3 + xr.w;
        *(float4*)(out + gbase + q*4) = o4;
    }
}

// ---------------------------------------------------------------------------
extern "C" void kernel_launch(void* const* d_in, const int* in_sizes, int n_in,
                              void* d_out, int out_size) {
    const float* x  = (const float*)d_in[0];
    const float* w1 = (const float*)d_in[1];
    const float* b1 = (const float*)d_in[2];
    const float* w2 = (const float*)d_in[3];
    const float* b2 = (const float*)d_in[4];
    const float* w3 = (const float*)d_in[5];
    const float* b3 = (const float*)d_in[6];
    const float* w4 = (const float*)d_in[7];
    const float* b4 = (const float*)d_in[8];
    const float* a1 = (const float*)d_in[9];
    const float* wc = (const float*)d_in[10];
    const float* bc = (const float*)d_in[11];
    const float* a2 = (const float*)d_in[12];
    float* out = (float*)d_out;

    pack_x<<<4096, 256>>>(x);
    pack_w<<<112, 256>>>(w1, w2, w3, w4, wc);
    branch_conv<<<dim3(4,128,8), 512>>>(b1, b2, b3, b4, a1);
    main_conv<<<dim3(4,128,8), 512>>>(x, bc, a2, out);
}